// round 7
// baseline (speedup 1.0000x reference)
#include <cuda_runtime.h>
#include <cuda_bf16.h>
#include <cstdint>
#include <math.h>

#define NB  32
#define NTQ 1024
#define NL  2048
#define ND  1024

// ===================== scratch =====================
static __device__ __nv_bfloat16 g_CatHi[(size_t)NB*NTQ*2*ND]; // cols 0..1023 = Q, 1024..2047 = attnA
static __device__ __nv_bfloat16 g_CatLo[(size_t)NB*NTQ*2*ND];
static __device__ __nv_bfloat16 g_QmHi [(size_t)NB*NTQ*ND];
static __device__ __nv_bfloat16 g_QmLo [(size_t)NB*NTQ*ND];
static __device__ __nv_bfloat16 g_KHi  [(size_t)NB*NL*ND];
static __device__ __nv_bfloat16 g_KLo  [(size_t)NB*NL*ND];
static __device__ __nv_bfloat16 g_VtHi [(size_t)NB*ND*NL];    // [b][DV][L]
static __device__ __nv_bfloat16 g_VtLo [(size_t)NB*ND*NL];
static __device__ __nv_bfloat16 g_AtHi [(size_t)NB*NTQ*NL];
static __device__ __nv_bfloat16 g_AtLo [(size_t)NB*NTQ*NL];
static __device__ __nv_bfloat16 g_WqHi [(size_t)ND*ND];
static __device__ __nv_bfloat16 g_WqLo [(size_t)ND*ND];
static __device__ __nv_bfloat16 g_WcHi [(size_t)ND*2*ND];
static __device__ __nv_bfloat16 g_WcLo [(size_t)ND*2*ND];
static __device__ float         g_ScFB [(size_t)NB*NTQ*NL];

// ===================== PTX =====================
__device__ __forceinline__ uint32_t smem_u32(const void* p){
    uint32_t a;
    asm("{ .reg .u64 t; cvta.to.shared.u64 t, %1; cvt.u32.u64 %0, t; }" : "=r"(a) : "l"(p));
    return a;
}
__device__ __forceinline__ void cpasync16(uint32_t s, const void* g){
    asm volatile("cp.async.cg.shared.global [%0], [%1], 16;" :: "r"(s), "l"(g) : "memory");
}
#define CP_COMMIT() asm volatile("cp.async.commit_group;" ::: "memory")
#define CP_WAIT(n)  asm volatile("cp.async.wait_group %0;" :: "n"(n) : "memory")

#define LDSM4(r0,r1,r2,r3,a) \
    asm volatile("ldmatrix.sync.aligned.m8n8.x4.shared.b16 {%0,%1,%2,%3}, [%4];" \
        : "=r"(r0),"=r"(r1),"=r"(r2),"=r"(r3) : "r"(a))

#define MMA(d, a, b0_, b1_) \
    asm volatile("mma.sync.aligned.m16n8k16.row.col.f32.bf16.bf16.f32 " \
        "{%0,%1,%2,%3},{%4,%5,%6,%7},{%8,%9},{%0,%1,%2,%3};" \
        : "+f"((d)[0]),"+f"((d)[1]),"+f"((d)[2]),"+f"((d)[3]) \
        : "r"((a)[0]),"r"((a)[1]),"r"((a)[2]),"r"((a)[3]),"r"(b0_),"r"(b1_))

__device__ __forceinline__ void split2(float x, __nv_bfloat16& h, __nv_bfloat16& l){
    h = __float2bfloat16(x);
    l = __float2bfloat16(x - __bfloat162float(h));
}

// ===================== conversion kernels =====================
// one float4 per thread; writes hi/lo bf16 with given col-shift / out ld
__device__ __forceinline__ void conv_one(const float4* in, __nv_bfloat16* hi,
                                         __nv_bfloat16* lo, long long i,
                                         int cshift, int outld)
{
    float4 v = in[i];
    long long e = i << 2;
    long long row = e >> cshift;
    int col = (int)(e & ((1LL << cshift) - 1));
    long long o = row * (long long)outld + col;
    __nv_bfloat16 h0,l0,h1,l1,h2,l2,h3,l3;
    split2(v.x,h0,l0); split2(v.y,h1,l1); split2(v.z,h2,l2); split2(v.w,h3,l3);
    __nv_bfloat162 a, b;
    a.x=h0; a.y=h1; *(__nv_bfloat162*)(hi+o)   = a;
    b.x=h2; b.y=h3; *(__nv_bfloat162*)(hi+o+2) = b;
    a.x=l0; a.y=l1; *(__nv_bfloat162*)(lo+o)   = a;
    b.x=l2; b.y=l3; *(__nv_bfloat162*)(lo+o+2) = b;
}

// fused split of Q, K, Wq, Wc in one launch (keeps GEMMs early in launch order
// so the ncu capture window lands on a GEMM)
static constexpr long long NQ4  = (long long)NB*NTQ*ND/4;     // 8388608
static constexpr long long NK4  = (long long)NB*NL*ND/4;      // 16777216
static constexpr long long NWQ4 = (long long)ND*ND/4;         // 262144
static constexpr long long NWC4 = (long long)ND*2*ND/4;       // 524288
static constexpr long long NTOT4 = NQ4 + NK4 + NWQ4 + NWC4;

__global__ __launch_bounds__(256)
void conv_all(const float4* __restrict__ Q,  const float4* __restrict__ K,
              const float4* __restrict__ Wq, const float4* __restrict__ Wc,
              __nv_bfloat16* __restrict__ CatHi, __nv_bfloat16* __restrict__ CatLo,
              __nv_bfloat16* __restrict__ KHi,   __nv_bfloat16* __restrict__ KLo,
              __nv_bfloat16* __restrict__ WqHi,  __nv_bfloat16* __restrict__ WqLo,
              __nv_bfloat16* __restrict__ WcHi,  __nv_bfloat16* __restrict__ WcLo)
{
    long long i = (long long)blockIdx.x * 256 + threadIdx.x;
    if (i < NQ4){ conv_one(Q, CatHi, CatLo, i, 10, 2*ND); return; }
    i -= NQ4;
    if (i < NK4){ conv_one(K, KHi, KLo, i, 10, ND); return; }
    i -= NK4;
    if (i < NWQ4){ conv_one(Wq, WqHi, WqLo, i, 10, ND); return; }
    i -= NWQ4;
    if (i < NWC4){ conv_one(Wc, WcHi, WcLo, i, 11, 2*ND); }
}

__global__ __launch_bounds__(256)
void vt_split(const float* __restrict__ V, __nv_bfloat16* __restrict__ Hi,
              __nv_bfloat16* __restrict__ Lo)
{
    __shared__ float t[32][33];
    const float* Vb = V + (long long)blockIdx.z * NL * ND;
    int v0 = blockIdx.x * 32, l0 = blockIdx.y * 32;
    int tx = threadIdx.x, ty = threadIdx.y;   // 32 x 8
    #pragma unroll
    for (int i = 0; i < 4; i++)
        t[ty + 8*i][tx] = Vb[(long long)(l0 + ty + 8*i) * ND + v0 + tx];
    __syncthreads();
    long long ob = (long long)blockIdx.z * ND * NL;
    #pragma unroll
    for (int i = 0; i < 4; i++){
        int vv = v0 + ty + 8*i, ll = l0 + tx;
        __nv_bfloat16 h, l; split2(t[tx][ty + 8*i], h, l);
        Hi[ob + (long long)vv * NL + ll] = h;
        Lo[ob + (long long)vv * NL + ll] = l;
    }
}

__global__ __launch_bounds__(256)
void softmax_split(float* __restrict__ S, __nv_bfloat16* __restrict__ Hi,
                   __nv_bfloat16* __restrict__ Lo)
{
    long long r = blockIdx.x;
    float* p = S + r * NL;
    const int tid = threadIdx.x, lane = tid & 31, wid = tid >> 5;
    float4 v0 = ((const float4*)p)[tid];
    float4 v1 = ((const float4*)p)[tid + 256];

    float mx = fmaxf(fmaxf(fmaxf(v0.x,v0.y),fmaxf(v0.z,v0.w)),
                     fmaxf(fmaxf(v1.x,v1.y),fmaxf(v1.z,v1.w)));
    __shared__ float red[8]; __shared__ float bval;
    #pragma unroll
    for (int o = 16; o > 0; o >>= 1) mx = fmaxf(mx, __shfl_xor_sync(0xffffffffu, mx, o));
    if (lane == 0) red[wid] = mx;
    __syncthreads();
    if (tid == 0){ float m = red[0];
        #pragma unroll
        for (int i = 1; i < 8; i++) m = fmaxf(m, red[i]); bval = m; }
    __syncthreads();
    mx = bval;
    v0.x = expf(v0.x-mx); v0.y = expf(v0.y-mx); v0.z = expf(v0.z-mx); v0.w = expf(v0.w-mx);
    v1.x = expf(v1.x-mx); v1.y = expf(v1.y-mx); v1.z = expf(v1.z-mx); v1.w = expf(v1.w-mx);
    float s = (v0.x+v0.y+v0.z+v0.w) + (v1.x+v1.y+v1.z+v1.w);
    #pragma unroll
    for (int o = 16; o > 0; o >>= 1) s += __shfl_xor_sync(0xffffffffu, s, o);
    if (lane == 0) red[wid] = s;
    __syncthreads();
    if (tid == 0){ float t = red[0];
        #pragma unroll
        for (int i = 1; i < 8; i++) t += red[i]; bval = 1.f/t; }
    __syncthreads();
    float inv = bval;
    v0.x*=inv; v0.y*=inv; v0.z*=inv; v0.w*=inv;
    v1.x*=inv; v1.y*=inv; v1.z*=inv; v1.w*=inv;
    ((float4*)p)[tid]       = v0;
    ((float4*)p)[tid + 256] = v1;

    __nv_bfloat16* hb = Hi + r * NL;
    __nv_bfloat16* lb = Lo + r * NL;
    __nv_bfloat16 h0,l0,h1,l1,h2,l2,h3,l3; __nv_bfloat162 a, b;
    int c0 = tid * 4, c1 = (tid + 256) * 4;
    split2(v0.x,h0,l0); split2(v0.y,h1,l1); split2(v0.z,h2,l2); split2(v0.w,h3,l3);
    a.x=h0; a.y=h1; *(__nv_bfloat162*)(hb+c0)   = a;
    b.x=h2; b.y=h3; *(__nv_bfloat162*)(hb+c0+2) = b;
    a.x=l0; a.y=l1; *(__nv_bfloat162*)(lb+c0)   = a;
    b.x=l2; b.y=l3; *(__nv_bfloat162*)(lb+c0+2) = b;
    split2(v1.x,h0,l0); split2(v1.y,h1,l1); split2(v1.z,h2,l2); split2(v1.w,h3,l3);
    a.x=h0; a.y=h1; *(__nv_bfloat162*)(hb+c1)   = a;
    b.x=h2; b.y=h3; *(__nv_bfloat162*)(hb+c1+2) = b;
    a.x=l0; a.y=l1; *(__nv_bfloat162*)(lb+c1)   = a;
    b.x=l2; b.y=l3; *(__nv_bfloat162*)(lb+c1+2) = b;
}

// ===================== warp-mma split-bf16 GEMM =====================
// C[m,n] = sum_k (Ah+Al)[m,k]*(Bh+Bl)[n,k], both K-major, f32 accum.
// products: AhBh + AhBl + AlBh.
// CTA tile 128x128, BK=32, 8 warps (2x4), warp tile 64x32, 3-stage cp.async
// with prefetch distance 2 (loads for stage s+2 issued BEFORE compute of s).
// smem rows padded to 80B: conflict-free ldmatrix.
static constexpr int ROWB   = 80;                 // padded row bytes (32 elems used)
static constexpr int MATB   = 128 * ROWB;         // 10240 B per matrix
static constexpr int STAGEB = 4 * MATB;           // Ah, Al, Bh, Bl = 40960 B
static constexpr int NSTG   = 3;
static constexpr int SMEMB  = NSTG * STAGEB;      // 122880 B

template<int EPI>   // 0: f32 C (+bias); 1: split bf16 C (+bias)
__global__ __launch_bounds__(256)
void mm_wm(const __nv_bfloat16* __restrict__ Ah, const __nv_bfloat16* __restrict__ Al,
           const __nv_bfloat16* __restrict__ Bh, const __nv_bfloat16* __restrict__ Bl,
           const float* __restrict__ bias,
           float* __restrict__ Cf, __nv_bfloat16* __restrict__ Ch, __nv_bfloat16* __restrict__ Cl,
           int Kd, int lda, int ldb, int ldc,
           long long sA, long long sB, long long sC)
{
    extern __shared__ char smem_raw[];
    const uint32_t smem = smem_u32(smem_raw);

    const int tid  = threadIdx.x;
    const int lane = tid & 31;
    const int wid  = tid >> 5;
    const int wm   = wid >> 2;          // 0..1
    const int wn   = wid & 3;           // 0..3
    const long long z = blockIdx.z;
    Ah += z * sA;  Al += z * sA;
    Bh += z * sB;  Bl += z * sB;
    if (EPI == 0) Cf += z * sC; else { Ch += z * sC; Cl += z * sC; }

    const long long m0 = (long long)blockIdx.y * 128;
    const int       n0 = blockIdx.x * 128;

    // ---- loader: 2048 x 16B chunks per stage, 8 per thread ----
    const __nv_bfloat16* srcA[2] = { Ah + m0 * lda, Al + m0 * lda };
    const __nv_bfloat16* srcB[2] = { Bh + (long long)n0 * ldb, Bl + (long long)n0 * ldb };

    auto loadStage = [&](int slot, int k0){
        const uint32_t base = smem + slot * STAGEB;
        #pragma unroll
        for (int it = 0; it < 8; it++){
            int idx  = tid + it * 256;
            int mat  = idx >> 9;          // 0..3: Ah, Al, Bh, Bl
            int rc   = idx & 511;
            int row  = rc >> 2;
            int ch   = rc & 3;
            const __nv_bfloat16* g =
                (mat < 2) ? (srcA[mat]     + (long long)row * lda + k0 + ch * 8)
                          : (srcB[mat - 2] + (long long)row * ldb + k0 + ch * 8);
            cpasync16(base + mat * MATB + row * ROWB + ch * 16, g);
        }
        CP_COMMIT();
    };

    float acc[4][4][4];
    #pragma unroll
    for (int i = 0; i < 4; i++)
        #pragma unroll
        for (int j = 0; j < 4; j++)
            #pragma unroll
            for (int r = 0; r < 4; r++) acc[i][j][r] = 0.f;

    const int S = Kd >> 5;
    loadStage(0, 0);
    if (S > 1) loadStage(1, 32);

    // per-lane ldmatrix base offsets
    const uint32_t aoff = (uint32_t)((wm * 64 + (lane & 15)) * ROWB + (lane >> 4) * 16);
    const uint32_t boff = (uint32_t)((wn * 32 + (lane & 15)) * ROWB + (lane >> 4) * 16);

    int slot = 0;
    for (int s = 0; s < S; s++){
        // prefetch stage s+2 BEFORE waiting/computing stage s
        // (slot (s+2)%3 readers finished at end of iter s-1; trailing
        //  __syncthreads of iter s-1 orders them before these writes)
        if (s + 2 < S){
            int ps = slot + 2; if (ps >= NSTG) ps -= NSTG;
            loadStage(ps, (s + 2) << 5);
            CP_WAIT(2);            // stage s complete (<=2 groups pending)
        } else if (s + 1 < S){
            CP_WAIT(1);
        } else {
            CP_WAIT(0);
        }
        __syncthreads();

        const uint32_t sb  = smem + slot * STAGEB;
        const uint32_t sAh = sb + aoff;
        const uint32_t sAl = sb + MATB + aoff;
        const uint32_t sBh = sb + 2 * MATB + boff;
        const uint32_t sBl = sb + 3 * MATB + boff;

        #pragma unroll
        for (int kc = 0; kc < 2; kc++){
            const uint32_t ko = (uint32_t)(kc * 32);
            uint32_t ah[4][4], al[4][4], bh[4][2], bl[4][2];
            #pragma unroll
            for (int i = 0; i < 4; i++){
                LDSM4(ah[i][0], ah[i][1], ah[i][2], ah[i][3], sAh + i * (16 * ROWB) + ko);
                LDSM4(al[i][0], al[i][1], al[i][2], al[i][3], sAl + i * (16 * ROWB) + ko);
            }
            {
                uint32_t q0,q1,q2,q3;
                LDSM4(q0,q1,q2,q3, sBh + ko);
                bh[0][0]=q0; bh[0][1]=q2; bh[1][0]=q1; bh[1][1]=q3;
                LDSM4(q0,q1,q2,q3, sBh + 16 * ROWB + ko);
                bh[2][0]=q0; bh[2][1]=q2; bh[3][0]=q1; bh[3][1]=q3;
                LDSM4(q0,q1,q2,q3, sBl + ko);
                bl[0][0]=q0; bl[0][1]=q2; bl[1][0]=q1; bl[1][1]=q3;
                LDSM4(q0,q1,q2,q3, sBl + 16 * ROWB + ko);
                bl[2][0]=q0; bl[2][1]=q2; bl[3][0]=q1; bl[3][1]=q3;
            }
            #pragma unroll
            for (int i = 0; i < 4; i++)
                #pragma unroll
                for (int j = 0; j < 4; j++){
                    MMA(acc[i][j], ah[i], bh[j][0], bh[j][1]);
                    MMA(acc[i][j], ah[i], bl[j][0], bl[j][1]);
                    MMA(acc[i][j], al[i], bh[j][0], bh[j][1]);
                }
        }
        __syncthreads();
        if (++slot >= NSTG) slot = 0;
    }

    // ---- epilogue ----
    #pragma unroll
    for (int i = 0; i < 4; i++){
        const long long r0 = m0 + wm * 64 + i * 16 + (lane >> 2);
        #pragma unroll
        for (int j = 0; j < 4; j++){
            const int c = n0 + wn * 32 + j * 8 + (lane & 3) * 2;
            float x0 = acc[i][j][0], x1 = acc[i][j][1];
            float x2 = acc[i][j][2], x3 = acc[i][j][3];
            if (bias){
                float b0 = bias[c], b1 = bias[c + 1];
                x0 += b0; x1 += b1; x2 += b0; x3 += b1;
            }
            if (EPI == 0){
                float2 u; u.x = x0; u.y = x1;
                *(float2*)(Cf + r0 * ldc + c) = u;
                u.x = x2; u.y = x3;
                *(float2*)(Cf + (r0 + 8) * ldc + c) = u;
            } else {
                __nv_bfloat16 h0,l0,h1,l1; __nv_bfloat162 hh, ll;
                split2(x0,h0,l0); split2(x1,h1,l1);
                hh.x=h0; hh.y=h1; *(__nv_bfloat162*)(Ch + r0 * ldc + c) = hh;
                ll.x=l0; ll.y=l1; *(__nv_bfloat162*)(Cl + r0 * ldc + c) = ll;
                split2(x2,h0,l0); split2(x3,h1,l1);
                hh.x=h0; hh.y=h1; *(__nv_bfloat162*)(Ch + (r0 + 8) * ldc + c) = hh;
                ll.x=l0; ll.y=l1; *(__nv_bfloat162*)(Cl + (r0 + 8) * ldc + c) = ll;
            }
        }
    }
}

// ===================== host =====================
extern "C" void kernel_launch(void* const* d_in, const int* in_sizes, int n_in,
                              void* d_out, int out_size)
{
    (void)in_sizes; (void)n_in;
    const float* Q   = (const float*)d_in[0];
    const float* Kin = (const float*)d_in[1];
    const float* V   = (const float*)d_in[2];
    const float* Wq  = (const float*)d_in[3];
    const float* bq  = (const float*)d_in[4];
    const float* Wc  = (const float*)d_in[5];
    const float* bc  = (const float*)d_in[6];
    float* out = (float*)d_out;

    __nv_bfloat16 *CatHi,*CatLo,*QmHi,*QmLo,*KHi,*KLo,*VtHi,*VtLo,*AtHi,*AtLo,*WqHi,*WqLo,*WcHi,*WcLo;
    float* ScFB;
    cudaGetSymbolAddress((void**)&CatHi, g_CatHi); cudaGetSymbolAddress((void**)&CatLo, g_CatLo);
    cudaGetSymbolAddress((void**)&QmHi,  g_QmHi ); cudaGetSymbolAddress((void**)&QmLo,  g_QmLo );
    cudaGetSymbolAddress((void**)&KHi,   g_KHi  ); cudaGetSymbolAddress((void**)&KLo,   g_KLo  );
    cudaGetSymbolAddress((void**)&VtHi,  g_VtHi ); cudaGetSymbolAddress((void**)&VtLo,  g_VtLo );
    cudaGetSymbolAddress((void**)&AtHi,  g_AtHi ); cudaGetSymbolAddress((void**)&AtLo,  g_AtLo );
    cudaGetSymbolAddress((void**)&WqHi,  g_WqHi ); cudaGetSymbolAddress((void**)&WqLo,  g_WqLo );
    cudaGetSymbolAddress((void**)&WcHi,  g_WcHi ); cudaGetSymbolAddress((void**)&WcLo,  g_WcLo );
    cudaGetSymbolAddress((void**)&ScFB,  g_ScFB );

    cudaFuncSetAttribute(mm_wm<0>, cudaFuncAttributeMaxDynamicSharedMemorySize, SMEMB);
    cudaFuncSetAttribute(mm_wm<1>, cudaFuncAttributeMaxDynamicSharedMemorySize, SMEMB);

    const long long outEl  = (long long)NB * NTQ * ND;
    const long long attnEl = (long long)NB * NTQ * NL;
    float* attn = ((long long)out_size >= outEl + attnEl) ? (out + outEl) : ScFB;

    // 0) fused conversions (1 launch) + V transpose (1 launch)
    conv_all<<<(unsigned)((NTOT4 + 255)/256), 256>>>(
        (const float4*)Q, (const float4*)Kin, (const float4*)Wq, (const float4*)Wc,
        CatHi, CatLo, KHi, KLo, WqHi, WqLo, WcHi, WcLo);
    vt_split<<<dim3(ND/32, NL/32, NB), dim3(32, 8)>>>(V, VtHi, VtLo);

    // 2) Qm = Q @ Wq^T + bq -> split bf16
    mm_wm<1><<<dim3(ND/128, (NB*NTQ)/128, 1), 256, SMEMB>>>(
        CatHi, CatLo, WqHi, WqLo, bq, nullptr, QmHi, QmLo,
        ND, 2*ND, ND, ND, 0, 0, 0);

    // 3) scores[b] = Qm[b] @ K[b]^T -> fp32 attn region
    mm_wm<0><<<dim3(NL/128, NTQ/128, NB), 256, SMEMB>>>(
        QmHi, QmLo, KHi, KLo, nullptr, attn, nullptr, nullptr,
        ND, ND, ND, NL, (long long)NTQ*ND, (long long)NL*ND, (long long)NTQ*NL);

    // 4) softmax (in place) + split to bf16
    softmax_split<<<NB*NTQ, 256>>>(attn, AtHi, AtLo);

    // 5) attnA[b] = P[b] @ Vt[b]^T -> Cat cols 1024..2047  (ncu capture target)
    mm_wm<1><<<dim3(ND/128, NTQ/128, NB), 256, SMEMB>>>(
        AtHi, AtLo, VtHi, VtLo, nullptr, nullptr, CatHi + ND, CatLo + ND,
        NL, NL, NL, 2*ND, (long long)NTQ*NL, (long long)ND*NL, (long long)NTQ*2*ND);

    // 6) out = Cat @ Wc^T + bc  (single K=2048 GEMM)
    mm_wm<0><<<dim3(ND/128, (NB*NTQ)/128, 1), 256, SMEMB>>>(
        CatHi, CatLo, WcHi, WcLo, bc, out, nullptr, nullptr,
        2*ND, 2*ND, 2*ND, ND, 0, 0, 0);
}

// round 8
// speedup vs baseline: 1.2958x; 1.2958x over previous
#include <cuda_runtime.h>
#include <cuda_bf16.h>
#include <cstdint>
#include <math.h>

#define NB  32
#define NTQ 1024
#define NL  2048
#define ND  1024

// ===================== scratch =====================
static __device__ __nv_bfloat16 g_CatHi[(size_t)NB*NTQ*2*ND]; // cols 0..1023 = Q, 1024..2047 = attnA
static __device__ __nv_bfloat16 g_CatLo[(size_t)NB*NTQ*2*ND];
static __device__ __nv_bfloat16 g_QmHi [(size_t)NB*NTQ*ND];
static __device__ __nv_bfloat16 g_QmLo [(size_t)NB*NTQ*ND];
static __device__ __nv_bfloat16 g_KHi  [(size_t)NB*NL*ND];
static __device__ __nv_bfloat16 g_KLo  [(size_t)NB*NL*ND];
static __device__ __nv_bfloat16 g_VtHi [(size_t)NB*ND*NL];    // [b][DV][L]
static __device__ __nv_bfloat16 g_VtLo [(size_t)NB*ND*NL];
static __device__ __nv_bfloat16 g_AtHi [(size_t)NB*NTQ*NL];
static __device__ __nv_bfloat16 g_AtLo [(size_t)NB*NTQ*NL];
static __device__ __nv_bfloat16 g_WqHi [(size_t)ND*ND];
static __device__ __nv_bfloat16 g_WqLo [(size_t)ND*ND];
static __device__ __nv_bfloat16 g_WcHi [(size_t)ND*2*ND];
static __device__ __nv_bfloat16 g_WcLo [(size_t)ND*2*ND];
static __device__ float         g_ScFB [(size_t)NB*NTQ*NL];

// ===================== PTX =====================
__device__ __forceinline__ uint32_t smem_u32(const void* p){
    uint32_t a;
    asm("{ .reg .u64 t; cvta.to.shared.u64 t, %1; cvt.u32.u64 %0, t; }" : "=r"(a) : "l"(p));
    return a;
}
__device__ __forceinline__ void cpasync16(uint32_t s, const void* g){
    asm volatile("cp.async.cg.shared.global [%0], [%1], 16;" :: "r"(s), "l"(g) : "memory");
}
#define CP_COMMIT() asm volatile("cp.async.commit_group;" ::: "memory")
#define CP_WAIT(n)  asm volatile("cp.async.wait_group %0;" :: "n"(n) : "memory")

#define LDSM4(r0,r1,r2,r3,a) \
    asm volatile("ldmatrix.sync.aligned.m8n8.x4.shared.b16 {%0,%1,%2,%3}, [%4];" \
        : "=r"(r0),"=r"(r1),"=r"(r2),"=r"(r3) : "r"(a))

#define MMA(d, a, b0_, b1_) \
    asm volatile("mma.sync.aligned.m16n8k16.row.col.f32.bf16.bf16.f32 " \
        "{%0,%1,%2,%3},{%4,%5,%6,%7},{%8,%9},{%0,%1,%2,%3};" \
        : "+f"((d)[0]),"+f"((d)[1]),"+f"((d)[2]),"+f"((d)[3]) \
        : "r"((a)[0]),"r"((a)[1]),"r"((a)[2]),"r"((a)[3]),"r"(b0_),"r"(b1_))

__device__ __forceinline__ void split2(float x, __nv_bfloat16& h, __nv_bfloat16& l){
    h = __float2bfloat16(x);
    l = __float2bfloat16(x - __bfloat162float(h));
}

// ===================== conversion kernels =====================
__device__ __forceinline__ void conv_one(const float4* in, __nv_bfloat16* hi,
                                         __nv_bfloat16* lo, long long i,
                                         int cshift, int outld)
{
    float4 v = in[i];
    long long e = i << 2;
    long long row = e >> cshift;
    int col = (int)(e & ((1LL << cshift) - 1));
    long long o = row * (long long)outld + col;
    __nv_bfloat16 h0,l0,h1,l1,h2,l2,h3,l3;
    split2(v.x,h0,l0); split2(v.y,h1,l1); split2(v.z,h2,l2); split2(v.w,h3,l3);
    __nv_bfloat162 a, b;
    a.x=h0; a.y=h1; *(__nv_bfloat162*)(hi+o)   = a;
    b.x=h2; b.y=h3; *(__nv_bfloat162*)(hi+o+2) = b;
    a.x=l0; a.y=l1; *(__nv_bfloat162*)(lo+o)   = a;
    b.x=l2; b.y=l3; *(__nv_bfloat162*)(lo+o+2) = b;
}

static constexpr long long NQ4  = (long long)NB*NTQ*ND/4;
static constexpr long long NK4  = (long long)NB*NL*ND/4;
static constexpr long long NWQ4 = (long long)ND*ND/4;
static constexpr long long NWC4 = (long long)ND*2*ND/4;
static constexpr long long NTOT4 = NQ4 + NK4 + NWQ4 + NWC4;

__global__ __launch_bounds__(256)
void conv_all(const float4* __restrict__ Q,  const float4* __restrict__ K,
              const float4* __restrict__ Wq, const float4* __restrict__ Wc,
              __nv_bfloat16* __restrict__ CatHi, __nv_bfloat16* __restrict__ CatLo,
              __nv_bfloat16* __restrict__ KHi,   __nv_bfloat16* __restrict__ KLo,
              __nv_bfloat16* __restrict__ WqHi,  __nv_bfloat16* __restrict__ WqLo,
              __nv_bfloat16* __restrict__ WcHi,  __nv_bfloat16* __restrict__ WcLo)
{
    long long i = (long long)blockIdx.x * 256 + threadIdx.x;
    if (i < NQ4){ conv_one(Q, CatHi, CatLo, i, 10, 2*ND); return; }
    i -= NQ4;
    if (i < NK4){ conv_one(K, KHi, KLo, i, 10, ND); return; }
    i -= NK4;
    if (i < NWQ4){ conv_one(Wq, WqHi, WqLo, i, 10, ND); return; }
    i -= NWQ4;
    if (i < NWC4){ conv_one(Wc, WcHi, WcLo, i, 11, 2*ND); }
}

__global__ __launch_bounds__(256)
void vt_split(const float* __restrict__ V, __nv_bfloat16* __restrict__ Hi,
              __nv_bfloat16* __restrict__ Lo)
{
    __shared__ float t[32][33];
    const float* Vb = V + (long long)blockIdx.z * NL * ND;
    int v0 = blockIdx.x * 32, l0 = blockIdx.y * 32;
    int tx = threadIdx.x, ty = threadIdx.y;   // 32 x 8
    #pragma unroll
    for (int i = 0; i < 4; i++)
        t[ty + 8*i][tx] = Vb[(long long)(l0 + ty + 8*i) * ND + v0 + tx];
    __syncthreads();
    long long ob = (long long)blockIdx.z * ND * NL;
    #pragma unroll
    for (int i = 0; i < 4; i++){
        int vv = v0 + ty + 8*i, ll = l0 + tx;
        __nv_bfloat16 h, l; split2(t[tx][ty + 8*i], h, l);
        Hi[ob + (long long)vv * NL + ll] = h;
        Lo[ob + (long long)vv * NL + ll] = l;
    }
}

__global__ __launch_bounds__(256)
void softmax_split(float* __restrict__ S, __nv_bfloat16* __restrict__ Hi,
                   __nv_bfloat16* __restrict__ Lo)
{
    long long r = blockIdx.x;
    float* p = S + r * NL;
    const int tid = threadIdx.x, lane = tid & 31, wid = tid >> 5;
    float4 v0 = ((const float4*)p)[tid];
    float4 v1 = ((const float4*)p)[tid + 256];

    float mx = fmaxf(fmaxf(fmaxf(v0.x,v0.y),fmaxf(v0.z,v0.w)),
                     fmaxf(fmaxf(v1.x,v1.y),fmaxf(v1.z,v1.w)));
    __shared__ float red[8]; __shared__ float bval;
    #pragma unroll
    for (int o = 16; o > 0; o >>= 1) mx = fmaxf(mx, __shfl_xor_sync(0xffffffffu, mx, o));
    if (lane == 0) red[wid] = mx;
    __syncthreads();
    if (tid == 0){ float m = red[0];
        #pragma unroll
        for (int i = 1; i < 8; i++) m = fmaxf(m, red[i]); bval = m; }
    __syncthreads();
    mx = bval;
    v0.x = expf(v0.x-mx); v0.y = expf(v0.y-mx); v0.z = expf(v0.z-mx); v0.w = expf(v0.w-mx);
    v1.x = expf(v1.x-mx); v1.y = expf(v1.y-mx); v1.z = expf(v1.z-mx); v1.w = expf(v1.w-mx);
    float s = (v0.x+v0.y+v0.z+v0.w) + (v1.x+v1.y+v1.z+v1.w);
    #pragma unroll
    for (int o = 16; o > 0; o >>= 1) s += __shfl_xor_sync(0xffffffffu, s, o);
    if (lane == 0) red[wid] = s;
    __syncthreads();
    if (tid == 0){ float t = red[0];
        #pragma unroll
        for (int i = 1; i < 8; i++) t += red[i]; bval = 1.f/t; }
    __syncthreads();
    float inv = bval;
    v0.x*=inv; v0.y*=inv; v0.z*=inv; v0.w*=inv;
    v1.x*=inv; v1.y*=inv; v1.z*=inv; v1.w*=inv;
    ((float4*)p)[tid]       = v0;
    ((float4*)p)[tid + 256] = v1;

    __nv_bfloat16* hb = Hi + r * NL;
    __nv_bfloat16* lb = Lo + r * NL;
    __nv_bfloat16 h0,l0,h1,l1,h2,l2,h3,l3; __nv_bfloat162 a, b;
    int c0 = tid * 4, c1 = (tid + 256) * 4;
    split2(v0.x,h0,l0); split2(v0.y,h1,l1); split2(v0.z,h2,l2); split2(v0.w,h3,l3);
    a.x=h0; a.y=h1; *(__nv_bfloat162*)(hb+c0)   = a;
    b.x=h2; b.y=h3; *(__nv_bfloat162*)(hb+c0+2) = b;
    a.x=l0; a.y=l1; *(__nv_bfloat162*)(lb+c0)   = a;
    b.x=l2; b.y=l3; *(__nv_bfloat162*)(lb+c0+2) = b;
    split2(v1.x,h0,l0); split2(v1.y,h1,l1); split2(v1.z,h2,l2); split2(v1.w,h3,l3);
    a.x=h0; a.y=h1; *(__nv_bfloat162*)(hb+c1)   = a;
    b.x=h2; b.y=h3; *(__nv_bfloat162*)(hb+c1+2) = b;
    a.x=l0; a.y=l1; *(__nv_bfloat162*)(lb+c1)   = a;
    b.x=l2; b.y=l3; *(__nv_bfloat162*)(lb+c1+2) = b;
}

// ===================== warp-mma split-bf16 GEMM =====================
// C[m,n] = sum_k (Ah+Al)[m,k]*(Bh+Bl)[n,k], K-major, f32 accum; AhBh+AhBl+AlBh.
// CTA tile 128x128, BK=32, 4 warps (2x2), warp tile 64x64, 2-stage cp.async.
// Paired-row XOR swizzle: rows 2p,2p+1 share a 128B line; 16B-chunk index
// c8 = (row&1)*4 + ch is XORed with (p&7). Conflict-free ldmatrix + stores.
static constexpr int MATB   = 128 * 64;           // 8192 B per matrix (no pad)
static constexpr int STAGEB = 4 * MATB;           // Ah, Al, Bh, Bl = 32768 B
static constexpr int SMEMB  = 2 * STAGEB;         // 65536 B

__device__ __forceinline__ uint32_t sw_addr(int row, int ch){
    int p = row >> 1;
    int c8 = ((row & 1) << 2) | ch;
    return (uint32_t)(p * 128 + ((c8 ^ (p & 7)) << 4));
}

template<int EPI>   // 0: f32 C (+bias); 1: split bf16 C (+bias)
__global__ __launch_bounds__(128, 2)
void mm_wm(const __nv_bfloat16* __restrict__ Ah, const __nv_bfloat16* __restrict__ Al,
           const __nv_bfloat16* __restrict__ Bh, const __nv_bfloat16* __restrict__ Bl,
           const float* __restrict__ bias,
           float* __restrict__ Cf, __nv_bfloat16* __restrict__ Ch, __nv_bfloat16* __restrict__ Cl,
           int Kd, int lda, int ldb, int ldc,
           long long sA, long long sB, long long sC)
{
    extern __shared__ char smem_raw[];
    const uint32_t smem = smem_u32(smem_raw);

    const int tid  = threadIdx.x;
    const int lane = tid & 31;
    const int wid  = tid >> 5;
    const int wm   = wid >> 1;          // 0..1
    const int wn   = wid & 1;           // 0..1
    const long long z = blockIdx.z;
    Ah += z * sA;  Al += z * sA;
    Bh += z * sB;  Bl += z * sB;
    if (EPI == 0) Cf += z * sC; else { Ch += z * sC; Cl += z * sC; }

    const long long m0 = (long long)blockIdx.y * 128;
    const int       n0 = blockIdx.x * 128;

    // ---- loader: 4 mats x 128 rows x 4 chunks = 2048 x 16B, 16 per thread ----
    const __nv_bfloat16* srcA[2] = { Ah + m0 * lda, Al + m0 * lda };
    const __nv_bfloat16* srcB[2] = { Bh + (long long)n0 * ldb, Bl + (long long)n0 * ldb };

    auto loadStage = [&](int slot, int k0){
        const uint32_t base = smem + slot * STAGEB;
        #pragma unroll
        for (int it = 0; it < 16; it++){
            int idx  = tid + it * 128;
            int mat  = idx >> 9;          // 0..3: Ah, Al, Bh, Bl
            int rc   = idx & 511;
            int row  = rc >> 2;
            int ch   = rc & 3;
            const __nv_bfloat16* g =
                (mat < 2) ? (srcA[mat]     + (long long)row * lda + k0 + ch * 8)
                          : (srcB[mat - 2] + (long long)row * ldb + k0 + ch * 8);
            cpasync16(base + mat * MATB + sw_addr(row, ch), g);
        }
        CP_COMMIT();
    };

    float acc[4][8][4];
    #pragma unroll
    for (int i = 0; i < 4; i++)
        #pragma unroll
        for (int j = 0; j < 8; j++)
            #pragma unroll
            for (int r = 0; r < 4; r++) acc[i][j][r] = 0.f;

    const int S = Kd >> 5;
    loadStage(0, 0);
    if (S > 1) loadStage(1, 32);

    // per-lane ldmatrix constants
    const int lr  = lane & 15;
    const int px  = (lr >> 1) & 7;            // (p & 7), same for A and B
    const int rb  = (lr & 1) << 2;            // row parity bit in c8
    const int chb = lane >> 4;                // 16B chunk select
    const uint32_t aBase = (uint32_t)(((wm * 64 + lr) >> 1) * 128);
    const uint32_t bBase = (uint32_t)(((wn * 64 + lr) >> 1) * 128);

    for (int s = 0; s < S; s++){
        if (s == S - 1) { CP_WAIT(0); } else { CP_WAIT(1); }
        __syncthreads();

        const uint32_t sb = smem + (s & 1) * STAGEB;
        #pragma unroll
        for (int kc = 0; kc < 2; kc++){
            const uint32_t sw = (uint32_t)(((rb | (kc * 2 + chb)) ^ px) << 4);
            uint32_t ah[4][4], al[4][4], bh[8][2], bl[8][2];
            #pragma unroll
            for (int i = 0; i < 4; i++){
                LDSM4(ah[i][0], ah[i][1], ah[i][2], ah[i][3],
                      sb + aBase + (uint32_t)(i * 1024) + sw);
                LDSM4(al[i][0], al[i][1], al[i][2], al[i][3],
                      sb + MATB + aBase + (uint32_t)(i * 1024) + sw);
            }
            #pragma unroll
            for (int j2 = 0; j2 < 4; j2++){
                uint32_t q0,q1,q2,q3;
                LDSM4(q0,q1,q2,q3, sb + 2*MATB + bBase + (uint32_t)(j2 * 1024) + sw);
                bh[2*j2][0]=q0; bh[2*j2][1]=q2; bh[2*j2+1][0]=q1; bh[2*j2+1][1]=q3;
                LDSM4(q0,q1,q2,q3, sb + 3*MATB + bBase + (uint32_t)(j2 * 1024) + sw);
                bl[2*j2][0]=q0; bl[2*j2][1]=q2; bl[2*j2+1][0]=q1; bl[2*j2+1][1]=q3;
            }
            #pragma unroll
            for (int i = 0; i < 4; i++)
                #pragma unroll
                for (int j = 0; j < 8; j++){
                    MMA(acc[i][j], ah[i], bh[j][0], bh[j][1]);
                    MMA(acc[i][j], ah[i], bl[j][0], bl[j][1]);
                    MMA(acc[i][j], al[i], bh[j][0], bh[j][1]);
                }
        }
        __syncthreads();
        if (s + 2 < S) loadStage(s & 1, (s + 2) << 5);
    }

    // ---- epilogue ----
    #pragma unroll
    for (int i = 0; i < 4; i++){
        const long long r0 = m0 + wm * 64 + i * 16 + (lane >> 2);
        #pragma unroll
        for (int j = 0; j < 8; j++){
            const int c = n0 + wn * 64 + j * 8 + (lane & 3) * 2;
            float x0 = acc[i][j][0], x1 = acc[i][j][1];
            float x2 = acc[i][j][2], x3 = acc[i][j][3];
            if (bias){
                float b0 = bias[c], b1 = bias[c + 1];
                x0 += b0; x1 += b1; x2 += b0; x3 += b1;
            }
            if (EPI == 0){
                float2 u; u.x = x0; u.y = x1;
                *(float2*)(Cf + r0 * ldc + c) = u;
                u.x = x2; u.y = x3;
                *(float2*)(Cf + (r0 + 8) * ldc + c) = u;
            } else {
                __nv_bfloat16 h0,l0,h1,l1; __nv_bfloat162 hh, ll;
                split2(x0,h0,l0); split2(x1,h1,l1);
                hh.x=h0; hh.y=h1; *(__nv_bfloat162*)(Ch + r0 * ldc + c) = hh;
                ll.x=l0; ll.y=l1; *(__nv_bfloat162*)(Cl + r0 * ldc + c) = ll;
                split2(x2,h0,l0); split2(x3,h1,l1);
                hh.x=h0; hh.y=h1; *(__nv_bfloat162*)(Ch + (r0 + 8) * ldc + c) = hh;
                ll.x=l0; ll.y=l1; *(__nv_bfloat162*)(Cl + (r0 + 8) * ldc + c) = ll;
            }
        }
    }
}

// ===================== host =====================
extern "C" void kernel_launch(void* const* d_in, const int* in_sizes, int n_in,
                              void* d_out, int out_size)
{
    (void)in_sizes; (void)n_in;
    const float* Q   = (const float*)d_in[0];
    const float* Kin = (const float*)d_in[1];
    const float* V   = (const float*)d_in[2];
    const float* Wq  = (const float*)d_in[3];
    const float* bq  = (const float*)d_in[4];
    const float* Wc  = (const float*)d_in[5];
    const float* bc  = (const float*)d_in[6];
    float* out = (float*)d_out;

    __nv_bfloat16 *CatHi,*CatLo,*QmHi,*QmLo,*KHi,*KLo,*VtHi,*VtLo,*AtHi,*AtLo,*WqHi,*WqLo,*WcHi,*WcLo;
    float* ScFB;
    cudaGetSymbolAddress((void**)&CatHi, g_CatHi); cudaGetSymbolAddress((void**)&CatLo, g_CatLo);
    cudaGetSymbolAddress((void**)&QmHi,  g_QmHi ); cudaGetSymbolAddress((void**)&QmLo,  g_QmLo );
    cudaGetSymbolAddress((void**)&KHi,   g_KHi  ); cudaGetSymbolAddress((void**)&KLo,   g_KLo  );
    cudaGetSymbolAddress((void**)&VtHi,  g_VtHi ); cudaGetSymbolAddress((void**)&VtLo,  g_VtLo );
    cudaGetSymbolAddress((void**)&AtHi,  g_AtHi ); cudaGetSymbolAddress((void**)&AtLo,  g_AtLo );
    cudaGetSymbolAddress((void**)&WqHi,  g_WqHi ); cudaGetSymbolAddress((void**)&WqLo,  g_WqLo );
    cudaGetSymbolAddress((void**)&WcHi,  g_WcHi ); cudaGetSymbolAddress((void**)&WcLo,  g_WcLo );
    cudaGetSymbolAddress((void**)&ScFB,  g_ScFB );

    cudaFuncSetAttribute(mm_wm<0>, cudaFuncAttributeMaxDynamicSharedMemorySize, SMEMB);
    cudaFuncSetAttribute(mm_wm<1>, cudaFuncAttributeMaxDynamicSharedMemorySize, SMEMB);

    const long long outEl  = (long long)NB * NTQ * ND;
    const long long attnEl = (long long)NB * NTQ * NL;
    float* attn = ((long long)out_size >= outEl + attnEl) ? (out + outEl) : ScFB;

    // 0) fused conversions + V transpose
    conv_all<<<(unsigned)((NTOT4 + 255)/256), 256>>>(
        (const float4*)Q, (const float4*)Kin, (const float4*)Wq, (const float4*)Wc,
        CatHi, CatLo, KHi, KLo, WqHi, WqLo, WcHi, WcLo);
    vt_split<<<dim3(ND/32, NL/32, NB), dim3(32, 8)>>>(V, VtHi, VtLo);

    // 2) Qm = Q @ Wq^T + bq -> split bf16
    mm_wm<1><<<dim3(ND/128, (NB*NTQ)/128, 1), 128, SMEMB>>>(
        CatHi, CatLo, WqHi, WqLo, bq, nullptr, QmHi, QmLo,
        ND, 2*ND, ND, ND, 0, 0, 0);

    // 3) scores[b] = Qm[b] @ K[b]^T -> fp32 attn region
    mm_wm<0><<<dim3(NL/128, NTQ/128, NB), 128, SMEMB>>>(
        QmHi, QmLo, KHi, KLo, nullptr, attn, nullptr, nullptr,
        ND, ND, ND, NL, (long long)NTQ*ND, (long long)NL*ND, (long long)NTQ*NL);

    // 4) softmax (in place) + split to bf16
    softmax_split<<<NB*NTQ, 256>>>(attn, AtHi, AtLo);

    // 5) attnA[b] = P[b] @ Vt[b]^T -> Cat cols 1024..2047  (ncu capture target)
    mm_wm<1><<<dim3(ND/128, NTQ/128, NB), 128, SMEMB>>>(
        AtHi, AtLo, VtHi, VtLo, nullptr, nullptr, CatHi + ND, CatLo + ND,
        NL, NL, NL, 2*ND, (long long)NTQ*NL, (long long)ND*NL, (long long)NTQ*2*ND);

    // 6) out = Cat @ Wc^T + bc  (single K=2048 GEMM)
    mm_wm<0><<<dim3(ND/128, (NB*NTQ)/128, 1), 128, SMEMB>>>(
        CatHi, CatLo, WcHi, WcLo, bc, out, nullptr, nullptr,
        2*ND, 2*ND, 2*ND, ND, 0, 0, 0);
}